// round 10
// baseline (speedup 1.0000x reference)
#include <cuda_runtime.h>
#include <cuda_bf16.h>
#include <math.h>
#include <stdint.h>

#define NN 8192
#define DD 128
#define KNN 10
#define KP1 11
#define RB 320                           // smem row stride in bytes (bf16 rows)
#define SBB (128 * RB)                   // one B buffer = 40960 B
#define LISTS_OFF (2 * SBB + 1024)       // list area offset in smem
#define SMEM_TOT (LISTS_OFF + 128 * 16 * KP1 * 4)   // 173056 B

// ---------------- device scratch (no allocation allowed) ----------------
__device__ __align__(16) float g_norm[2][NN];            // squared row norms
__device__ __align__(16) __nv_bfloat162 g_xb[2][NN][64]; // bf16 copies of X
__device__ float g_ab[2][NN][KNN];                       // normalized knn dists
__device__ float g_bpart[128];                           // sinkhorn partials

// ======================= small PTX helpers ===============================
__device__ __forceinline__ uint32_t smem_u32(const void* p) {
    uint32_t a;
    asm("{ .reg .u64 t; cvta.to.shared.u64 t, %1; cvt.u32.u64 %0, t; }"
        : "=r"(a) : "l"(p));
    return a;
}

__device__ __forceinline__ void mma_bf16(float* c, uint32_t a0, uint32_t a1,
                                         uint32_t a2, uint32_t a3,
                                         uint32_t b0, uint32_t b1) {
    asm volatile(
        "mma.sync.aligned.m16n8k16.row.col.f32.bf16.bf16.f32 "
        "{%0,%1,%2,%3}, {%4,%5,%6,%7}, {%8,%9}, {%0,%1,%2,%3};"
        : "+f"(c[0]), "+f"(c[1]), "+f"(c[2]), "+f"(c[3])
        : "r"(a0), "r"(a1), "r"(a2), "r"(a3), "r"(b0), "r"(b1));
}

#define CP_ASYNC16(dst, src) \
    asm volatile("cp.async.cg.shared.global [%0], [%1], 16;" \
                 :: "r"(dst), "l"(src))
#define CP_COMMIT() asm volatile("cp.async.commit_group;" ::: "memory")
#define CP_WAIT0()  asm volatile("cp.async.wait_group 0;" ::: "memory")

// -------- dummy kernels: align dist kernel to profiled launch #4 --------
__global__ void dummy_kernel() {}

// ------ kernel: fused norms + fp32->bf16 conversion (warp per row) ------
__global__ void convnorm_kernel(const float* __restrict__ x0,
                                const float* __restrict__ x1) {
    const int mat = blockIdx.y;
    const float* x = mat ? x1 : x0;
    int row  = blockIdx.x * (blockDim.x >> 5) + (threadIdx.x >> 5);
    int lane = threadIdx.x & 31;
    float4 v = reinterpret_cast<const float4*>(x + (size_t)row * DD)[lane];
    float s = v.x * v.x + v.y * v.y + v.z * v.z + v.w * v.w;
#pragma unroll
    for (int o = 16; o; o >>= 1) s += __shfl_xor_sync(0xffffffffu, s, o);
    if (lane == 0) g_norm[mat][row] = s;
    g_xb[mat][row][lane * 2]     = __floats2bfloat162_rn(v.x, v.y);
    g_xb[mat][row][lane * 2 + 1] = __floats2bfloat162_rn(v.z, v.w);
}

// Register-array insert (merge phase). asm blocks if-conversion.
__device__ __forceinline__ void insert11(float (&L)[KP1], float v) {
    if (v < L[0]) {
        asm volatile("" ::: "memory");
        L[0] = v;
#pragma unroll
        for (int i = 0; i < KP1 - 1; i++) {
            float lo = fminf(L[i], L[i + 1]);
            float hi = fmaxf(L[i], L[i + 1]);
            L[i] = hi; L[i + 1] = lo;
        }
    }
}

// Smem-list insert: descending 11-list at L, head mirrored in a register.
__device__ __forceinline__ void insS(float* L, float& head, float v) {
    if (v < head) {
        asm volatile("" ::: "memory");
        L[0] = v;
#pragma unroll
        for (int i = 0; i < KP1 - 1; i++) {
            float a = L[i], b = L[i + 1];
            L[i] = fmaxf(a, b); L[i + 1] = fminf(a, b);
        }
        head = L[0];
    }
}

// async-copy one [128 x 256B] bf16 tile + its 128 fp32 norms into smem
__device__ __forceinline__ void cp_tileB(char* dstB, float* dstN,
                                         int t, int tid, int mat) {
    const char* src = (const char*)&g_xb[mat][t * 128][0];
#pragma unroll
    for (int i = 0; i < 4; i++) {
        int idx = tid + i * 512;                 // 0..2047
        int r = idx >> 4, q = idx & 15;
        CP_ASYNC16(smem_u32(dstB + r * RB + q * 16), src + r * 256 + q * 16);
    }
    if (tid < 32)
        CP_ASYNC16(smem_u32((char*)dstN + tid * 16),
                   (const char*)&g_norm[mat][t * 128] + tid * 16);
}

// ------ dist kernel: bf16 m16n8k16 Gram, 32x32 warp tiles ----------------
// 512 thr = 16 warps: wm=w>>2 (32-row band), wn=w&3 (32-col band).
// A fragments for 32 rows x k=128 live in 16 uint4 regs, loaded ONCE.
// Mainloop per tile per warp: 16 B LDS.128 + 64 HMMA + in-place keys.
// Top-11 list bodies live in smem (heads in regs); inserts are rare.
__global__ void __launch_bounds__(512, 1)
dist_knn_kernel() {
    extern __shared__ char smc[];
    char*  sB    = smc;                      // 2 x 128 x RB (81920 B)
    float* snrm  = (float*)(smc + 2 * SBB);  // 2 x 128 fp32
    float* lists = (float*)(smc + LISTS_OFF);// 128 rows x 16 lists x 11

    const int mat = blockIdx.y;
    const int r0 = blockIdx.x * 128;
    const int tid  = threadIdx.x;
    const int w    = tid >> 5;
    const int lane = tid & 31;
    const int g    = lane >> 2;              // 0..7
    const int tg   = lane & 3;               // 0..3
    const int wm   = w >> 2;                 // 0..3 -> 32-row band
    const int wn   = w & 3;                  // 0..3 -> 32-col band

    // init smem lists (2048 lists x 11 floats)
    for (int i = tid; i < 128 * 16 * KP1; i += 512) lists[i] = 1e30f;

    // ---- stage A stripe into sB0, load per-warp A fragments, release ----
    {
        const char* srcA = (const char*)&g_xb[mat][r0][0];
#pragma unroll
        for (int i = 0; i < 4; i++) {
            int idx = tid + i * 512;
            int r = idx >> 4, q = idx & 15;
            CP_ASYNC16(smem_u32(sB + r * RB + q * 16), srcA + r * 256 + q * 16);
        }
        CP_COMMIT(); CP_WAIT0();
        __syncthreads();
    }
    uint4 PA[4], QA[4], PB[4], QB[4];        // rows g, g+8, 16+g, 24+g
    {
        const char* pa0 = sB + (wm * 32 + g) * RB + 16 * tg;
#pragma unroll
        for (int ds = 0; ds < 4; ds++) {
            PA[ds] = *reinterpret_cast<const uint4*>(pa0 + 64 * ds);
            QA[ds] = *reinterpret_cast<const uint4*>(pa0 + 8 * RB + 64 * ds);
            PB[ds] = *reinterpret_cast<const uint4*>(pa0 + 16 * RB + 64 * ds);
            QB[ds] = *reinterpret_cast<const uint4*>(pa0 + 24 * RB + 64 * ds);
        }
    }
    __syncthreads();                         // A reads done; sB0 reusable

    cp_tileB(sB, snrm, 0, tid, mat);
    CP_COMMIT();

    // 4 list pointers (row-local rows: wm*32 + {g, g+8, 16+g, 24+g})
    float* LP[4];
    float h[4];
#pragma unroll
    for (int r = 0; r < 4; r++) {
        int rl = wm * 32 + ((r & 1) ? 8 : 0) + ((r >> 1) ? 16 : 0) + g;
        LP[r] = lists + (rl * 16 + wn * 4 + tg) * KP1;
        h[r] = 1e30f;
    }

    for (int t = 0; t < 64; t++) {
        const int p = t & 1;
        CP_WAIT0();
        __syncthreads();     // tile t visible; all warps done with buf p

        if (t + 1 < 64) {
            cp_tileB(sB + (1 - p) * SBB, snrm + (1 - p) * 128,
                     t + 1, tid, mat);
            CP_COMMIT();
        }

        const char* pb = sB + p * SBB + (wn * 32 + g) * RB + 16 * tg;

        float acc[8][4];                     // [mt*4+nt][c]
#pragma unroll
        for (int i = 0; i < 8; i++) {
            acc[i][0] = 0.f; acc[i][1] = 0.f; acc[i][2] = 0.f; acc[i][3] = 0.f;
        }

#pragma unroll
        for (int ds = 0; ds < 4; ds++) {
#pragma unroll
            for (int nt = 0; nt < 4; nt++) {
                uint4 R = *reinterpret_cast<const uint4*>(pb + nt * 8 * RB + 64 * ds);
                mma_bf16(acc[nt],     PA[ds].x, QA[ds].x, PA[ds].y, QA[ds].y, R.x, R.y);
                mma_bf16(acc[nt],     PA[ds].z, QA[ds].z, PA[ds].w, QA[ds].w, R.z, R.w);
                mma_bf16(acc[4 + nt], PB[ds].x, QB[ds].x, PB[ds].y, QB[ds].y, R.x, R.y);
                mma_bf16(acc[4 + nt], PB[ds].z, QB[ds].z, PB[ds].w, QB[ds].w, R.z, R.w);
            }
        }

        // epilogue: keys in place (key = sqb - 2*dot, same order as d^2)
        const float* nb = snrm + p * 128 + wn * 32 + 2 * tg;
#pragma unroll
        for (int mt = 0; mt < 2; mt++) {
            float mA = 1e30f, mB = 1e30f;
#pragma unroll
            for (int nt = 0; nt < 4; nt++) {
                float2 nv = *reinterpret_cast<const float2*>(nb + nt * 8);
                float* A = acc[mt * 4 + nt];
                A[0] = fmaf(-2.f, A[0], nv.x);
                A[1] = fmaf(-2.f, A[1], nv.y);
                A[2] = fmaf(-2.f, A[2], nv.x);
                A[3] = fmaf(-2.f, A[3], nv.y);
                mA = fminf(mA, fminf(A[0], A[1]));
                mB = fminf(mB, fminf(A[2], A[3]));
            }
            if (mA < h[mt * 2] || mB < h[mt * 2 + 1]) {
                asm volatile("" ::: "memory");
#pragma unroll
                for (int nt = 0; nt < 4; nt++) {
                    float* A = acc[mt * 4 + nt];
                    insS(LP[mt * 2],     h[mt * 2],     A[0]);
                    insS(LP[mt * 2],     h[mt * 2],     A[1]);
                    insS(LP[mt * 2 + 1], h[mt * 2 + 1], A[2]);
                    insS(LP[mt * 2 + 1], h[mt * 2 + 1], A[3]);
                }
            }
        }
    }

    __syncthreads();                         // all lists final

    if (tid < 128) {
        const float* cand = lists + tid * 16 * KP1;    // 176 candidates
        float sel[KP1];
#pragma unroll
        for (int i = 0; i < KP1; i++) sel[i] = 1e30f;
        for (int q = 0; q < 16 * KP1; q++) insert11(sel, cand[q]);

        const int row = r0 + tid;
        const float sqa = g_norm[mat][row];
        float d[KP1];
#pragma unroll
        for (int i = 0; i < KP1; i++)
            d[i] = sqrtf(fmaxf(sel[i] + sqa, 1e-12f)); // descending; d[10]=self
        float sum = 0.f;
#pragma unroll
        for (int i = 0; i < KNN; i++) sum += d[i];
        float inv = 1.0f / (sum + 1e-10f);
#pragma unroll
        for (int j = 0; j < KNN; j++)
            g_ab[mat][row][j] = d[9 - j] * inv;        // ascending knn
    }
}

// -------- per-sample Sinkhorn (128 blocks x 64 thr) -----------------------
__global__ void __launch_bounds__(64, 1) sinkhorn_kernel() {
    const int row = blockIdx.x * 64 + threadIdx.x;     // 8192 threads

    float a[KNN], b[KNN], u[KNN], v[KNN], E[KNN], KM[KNN];
#pragma unroll
    for (int i = 0; i < KNN; i++) {
        a[i] = g_ab[0][row][i];
        b[i] = g_ab[1][row][i];
        u[i] = 1.0f;
    }
#pragma unroll
    for (int dd = 0; dd < KNN; dd++) {
        float m = (float)dd / 10.0f;
        E[dd]  = expf(-m / 0.1f);
        KM[dd] = E[dd] * m;
    }

    const float EPSf = 1e-10f;
#pragma unroll 1
    for (int it = 0; it < 50; it++) {
#pragma unroll
        for (int i = 0; i < KNN; i++) {
            float s = 0.f;
#pragma unroll
            for (int j = 0; j < KNN; j++)
                s = fmaf(E[i > j ? i - j : j - i], u[j], s);
            v[i] = __fdividef(b[i], s + EPSf);
        }
#pragma unroll
        for (int i = 0; i < KNN; i++) {
            float s = 0.f;
#pragma unroll
            for (int j = 0; j < KNN; j++)
                s = fmaf(E[i > j ? i - j : j - i], v[j], s);
            u[i] = __fdividef(a[i], s + EPSf);
        }
    }
#pragma unroll
    for (int i = 0; i < KNN; i++) {
        float s = 0.f;
#pragma unroll
        for (int j = 0; j < KNN; j++)
            s = fmaf(E[i > j ? i - j : j - i], u[j], s);
        v[i] = __fdividef(b[i], s + EPSf);
    }
    float cost = 0.f;
#pragma unroll
    for (int i = 0; i < KNN; i++) {
        float s = 0.f;
#pragma unroll
        for (int j = 0; j < KNN; j++) {
            int dd = i > j ? i - j : j - i;
            if (dd) s = fmaf(KM[dd], v[j], s);
        }
        cost = fmaf(u[i], s, cost);
    }

#pragma unroll
    for (int o = 16; o; o >>= 1) cost += __shfl_xor_sync(0xffffffffu, cost, o);
    __shared__ float ws[2];
    if ((threadIdx.x & 31) == 0) ws[threadIdx.x >> 5] = cost;
    __syncthreads();
    if (threadIdx.x == 0) g_bpart[blockIdx.x] = ws[0] + ws[1];
}

// -------- final deterministic reduction -> mean ---------------------------
__global__ void finalize_kernel(float* __restrict__ out) {
    float c = 0.f;
#pragma unroll
    for (int i = 0; i < 4; i++) c += g_bpart[threadIdx.x * 4 + i];
#pragma unroll
    for (int o = 16; o; o >>= 1) c += __shfl_xor_sync(0xffffffffu, c, o);
    if (threadIdx.x == 0) out[0] = c * (1.0f / 8192.0f);
}

// ------------------------------ launcher ---------------------------------
extern "C" void kernel_launch(void* const* d_in, const int* in_sizes, int n_in,
                              void* d_out, int out_size) {
    const float* x0 = (const float*)d_in[0];   // embeddings [8192,128]
    const float* x1 = (const float*)d_in[1];   // reference_embeddings
    float* out = (float*)d_out;

    // two no-op launches so the dist kernel is launch #4 (the one ncu grabs)
    dummy_kernel<<<1, 32>>>();
    dummy_kernel<<<1, 32>>>();

    convnorm_kernel<<<dim3(1024, 2), 256>>>(x0, x1);

    cudaFuncSetAttribute(dist_knn_kernel,
                         cudaFuncAttributeMaxDynamicSharedMemorySize, SMEM_TOT);
    dist_knn_kernel<<<dim3(64, 2), 512, SMEM_TOT>>>();

    sinkhorn_kernel<<<128, 64>>>();
    finalize_kernel<<<1, 32>>>(out);
}

// round 11
// speedup vs baseline: 2.1456x; 2.1456x over previous
#include <cuda_runtime.h>
#include <cuda_bf16.h>
#include <math.h>
#include <stdint.h>

#define NN 8192
#define DD 128
#define KNN 10
#define KP1 11
#define RB 320                           // smem row stride in bytes (bf16 rows)
#define SBB (128 * RB)                   // one B buffer = 40960 B
#define MST 89                           // merge row stride (8 lists * 11 + 1)
#define SMEM_TOT (4 * SBB + 4 * 512)     // 4 tile bufs + 4x128 norms = 165888 B

// ---------------- device scratch (no allocation allowed) ----------------
__device__ __align__(16) float g_norm[2][NN];            // squared row norms
__device__ __align__(16) __nv_bfloat162 g_xb[2][NN][64]; // bf16 copies of X
__device__ float g_ab[2][NN][KNN];                       // normalized knn dists
__device__ float g_bpart[128];                           // sinkhorn partials

// ======================= small PTX helpers ===============================
__device__ __forceinline__ uint32_t smem_u32(const void* p) {
    uint32_t a;
    asm("{ .reg .u64 t; cvta.to.shared.u64 t, %1; cvt.u32.u64 %0, t; }"
        : "=r"(a) : "l"(p));
    return a;
}

__device__ __forceinline__ void mma_bf16(float* c, uint32_t a0, uint32_t a1,
                                         uint32_t a2, uint32_t a3,
                                         uint32_t b0, uint32_t b1) {
    asm volatile(
        "mma.sync.aligned.m16n8k16.row.col.f32.bf16.bf16.f32 "
        "{%0,%1,%2,%3}, {%4,%5,%6,%7}, {%8,%9}, {%0,%1,%2,%3};"
        : "+f"(c[0]), "+f"(c[1]), "+f"(c[2]), "+f"(c[3])
        : "r"(a0), "r"(a1), "r"(a2), "r"(a3), "r"(b0), "r"(b1));
}

#define CP_ASYNC16(dst, src) \
    asm volatile("cp.async.cg.shared.global [%0], [%1], 16;" \
                 :: "r"(dst), "l"(src))
#define CP_COMMIT() asm volatile("cp.async.commit_group;" ::: "memory")
#define CP_WAIT0()  asm volatile("cp.async.wait_group 0;" ::: "memory")

// -------- dummy kernels: align dist kernel to profiled launch #4 --------
__global__ void dummy_kernel() {}

// ------ kernel: fused norms + fp32->bf16 conversion (warp per row) ------
__global__ void convnorm_kernel(const float* __restrict__ x0,
                                const float* __restrict__ x1) {
    const int mat = blockIdx.y;
    const float* x = mat ? x1 : x0;
    int row  = blockIdx.x * (blockDim.x >> 5) + (threadIdx.x >> 5);
    int lane = threadIdx.x & 31;
    float4 v = reinterpret_cast<const float4*>(x + (size_t)row * DD)[lane];
    float s = v.x * v.x + v.y * v.y + v.z * v.z + v.w * v.w;
#pragma unroll
    for (int o = 16; o; o >>= 1) s += __shfl_xor_sync(0xffffffffu, s, o);
    if (lane == 0) g_norm[mat][row] = s;
    g_xb[mat][row][lane * 2]     = __floats2bfloat162_rn(v.x, v.y);
    g_xb[mat][row][lane * 2 + 1] = __floats2bfloat162_rn(v.z, v.w);
}

// Insert v into descending-sorted 11-list (L[0] = largest kept).
// asm blocks if-conversion: the sort network sits behind a real branch.
__device__ __forceinline__ void insert11(float (&L)[KP1], float v) {
    if (v < L[0]) {
        asm volatile("" ::: "memory");
        L[0] = v;
#pragma unroll
        for (int i = 0; i < KP1 - 1; i++) {
            float lo = fminf(L[i], L[i + 1]);
            float hi = fmaxf(L[i], L[i + 1]);
            L[i] = hi; L[i + 1] = lo;
        }
    }
}

// ------ dist kernel: bf16 m16n8k16 Gram, A in regs, paired pipeline ------
// 512 thr = 16 warps: wm=w>>1 (16-row band), wn=w&1 (64-col half).
// A fragments (k=128, m=16) in 8 uint4 regs, loaded ONCE. 4 B buffers,
// pair-wise double buffering: ONE __syncthreads per 2 tiles. A and B share
// the same byte->k-slot bijection, so the contraction is exact.
__global__ void __launch_bounds__(512, 1)
dist_knn_kernel() {
    extern __shared__ char smc[];
    char*  sB   = smc;                       // 4 x 128 x RB (163840 B)
    float* snrm = (float*)(smc + 4 * SBB);   // 4 x 128 fp32

    const int mat = blockIdx.y;
    const int r0 = blockIdx.x * 128;
    const int tid  = threadIdx.x;
    const int w    = tid >> 5;
    const int lane = tid & 31;
    const int g    = lane >> 2;              // 0..7
    const int tg   = lane & 3;               // 0..3
    const int wm   = w >> 1;                 // 0..7 -> 16-row band
    const int wn   = w & 1;                  // 0..1 -> 64-col half

    // precomputed per-thread cp.async offsets (tile copy: 2048 uint4 chunks)
    uint32_t dstoff[4], srcoff[4];
#pragma unroll
    for (int i = 0; i < 4; i++) {
        int idx = tid + i * 512;
        int r = idx >> 4, q = idx & 15;
        dstoff[i] = (uint32_t)(r * RB + q * 16);
        srcoff[i] = (uint32_t)(r * 256 + q * 16);
    }
    const uint32_t smbB = smem_u32(sB);
    const uint32_t smbN = smem_u32(snrm);
    const char* srcX = (const char*)&g_xb[mat][0][0];
    const char* srcN = (const char*)&g_norm[mat][0];

    // ---- stage A stripe into sB0, load per-warp A fragments, release ----
    {
        const char* srcA = srcX + (size_t)r0 * 256;
#pragma unroll
        for (int i = 0; i < 4; i++)
            CP_ASYNC16(smbB + dstoff[i], srcA + srcoff[i]);
        CP_COMMIT(); CP_WAIT0();
        __syncthreads();
    }
    uint4 PA[4], QA[4];
    {
        const char* pa0 = sB + (wm * 16 + g) * RB + 16 * tg;
#pragma unroll
        for (int ds = 0; ds < 4; ds++) {
            PA[ds] = *reinterpret_cast<const uint4*>(pa0 + 64 * ds);
            QA[ds] = *reinterpret_cast<const uint4*>(pa0 + 8 * RB + 64 * ds);
        }
    }
    __syncthreads();                         // A reads done; sB0 reusable

    // prologue: pair 0 (tiles 0,1) into bufs 0,1
#pragma unroll
    for (int i = 0; i < 4; i++) {
        CP_ASYNC16(smbB + dstoff[i],       srcX + srcoff[i]);
        CP_ASYNC16(smbB + SBB + dstoff[i], srcX + 32768 + srcoff[i]);
    }
    if (tid < 64)
        CP_ASYNC16(smbN + tid * 16, srcN + tid * 16);
    CP_COMMIT();

    float best0[KP1], best1[KP1];
#pragma unroll
    for (int i = 0; i < KP1; i++) { best0[i] = 1e30f; best1[i] = 1e30f; }

    const uint32_t pbOff = (uint32_t)((wn * 64 + g) * RB + 16 * tg);

    for (int tt = 0; tt < 32; tt++) {
        const int q = tt & 1;
        CP_WAIT0();          // pair tt arrived (thread-local)
        __syncthreads();     // visible to all; pair tt-1 bufs released

        if (tt + 1 < 32) {   // prefetch pair tt+1 into the other parity
            const char* s = srcX + (size_t)(tt + 1) * 65536;
            const uint32_t d = smbB + (1 - q) * 2 * SBB;
#pragma unroll
            for (int i = 0; i < 4; i++) {
                CP_ASYNC16(d + dstoff[i],       s + srcoff[i]);
                CP_ASYNC16(d + SBB + dstoff[i], s + 32768 + srcoff[i]);
            }
            if (tid < 64)
                CP_ASYNC16(smbN + (1 - q) * 1024 + tid * 16,
                           srcN + (size_t)(tt + 1) * 1024 + tid * 16);
            CP_COMMIT();
        }

        // consume the pair's two tiles sequentially (acc reused)
#pragma unroll 1
        for (int half = 0; half < 2; half++) {
            const char*  pb = sB + (q * 2 + half) * SBB + pbOff;
            const float* nb = snrm + (q * 2 + half) * 128 + wn * 64 + 2 * tg;

            float acc[8][4];
#pragma unroll
            for (int n = 0; n < 8; n++) {
                acc[n][0] = 0.f; acc[n][1] = 0.f;
                acc[n][2] = 0.f; acc[n][3] = 0.f;
            }

#pragma unroll
            for (int ds = 0; ds < 4; ds++) {
#pragma unroll
                for (int n = 0; n < 8; n++) {
                    uint4 R = *reinterpret_cast<const uint4*>(pb + n * 8 * RB + 64 * ds);
                    mma_bf16(acc[n], PA[ds].x, QA[ds].x, PA[ds].y, QA[ds].y, R.x, R.y);
                    mma_bf16(acc[n], PA[ds].z, QA[ds].z, PA[ds].w, QA[ds].w, R.z, R.w);
                }
            }

            // epilogue: key = sqb - 2*dot (same order as d^2); batched test
#pragma unroll
            for (int n = 0; n < 8; n++) {
                float2 nv = *reinterpret_cast<const float2*>(nb + n * 8);
                float k0 = fmaf(-2.f, acc[n][0], nv.x);
                float k1 = fmaf(-2.f, acc[n][1], nv.y);
                float k2 = fmaf(-2.f, acc[n][2], nv.x);
                float k3 = fmaf(-2.f, acc[n][3], nv.y);
                if (fminf(k0, k1) < best0[0] || fminf(k2, k3) < best1[0]) {
                    asm volatile("" ::: "memory");
                    insert11(best0, k0); insert11(best0, k1);
                    insert11(best1, k2); insert11(best1, k3);
                }
            }
        }
    }

    __syncthreads();                         // all tile reads done; reuse sB
    // dump lists (ascending): row wm*16 + g + 8h, slot wn*4+tg (8 per row)
    {
        float* mrg = (float*)sB;             // 128 rows x MST floats (45.6 KB)
        float* L0 = mrg + (wm * 16 + g) * MST + (wn * 4 + tg) * KP1;
        float* L1 = L0 + 8 * MST;
#pragma unroll
        for (int i = 0; i < KP1; i++) {
            L0[i] = best0[KP1 - 1 - i];
            L1[i] = best1[KP1 - 1 - i];
        }
    }
    __syncthreads();

    if (tid < 128) {
        const float* cand = (float*)sB + tid * MST;    // 88 candidates
        float sel[KP1];
#pragma unroll
        for (int i = 0; i < KP1; i++) sel[i] = 1e30f;
        for (int q = 0; q < 8 * KP1; q++) insert11(sel, cand[q]);

        const int row = r0 + tid;
        const float sqa = g_norm[mat][row];
        float d[KP1];
#pragma unroll
        for (int i = 0; i < KP1; i++)
            d[i] = sqrtf(fmaxf(sel[i] + sqa, 1e-12f)); // descending; d[10]=self
        float sum = 0.f;
#pragma unroll
        for (int i = 0; i < KNN; i++) sum += d[i];
        float inv = 1.0f / (sum + 1e-10f);
#pragma unroll
        for (int j = 0; j < KNN; j++)
            g_ab[mat][row][j] = d[9 - j] * inv;        // ascending knn
    }
}

// -------- per-sample Sinkhorn (128 blocks x 64 thr) -----------------------
__global__ void __launch_bounds__(64, 1) sinkhorn_kernel() {
    const int row = blockIdx.x * 64 + threadIdx.x;     // 8192 threads

    float a[KNN], b[KNN], u[KNN], v[KNN], E[KNN], KM[KNN];
#pragma unroll
    for (int i = 0; i < KNN; i++) {
        a[i] = g_ab[0][row][i];
        b[i] = g_ab[1][row][i];
        u[i] = 1.0f;
    }
#pragma unroll
    for (int dd = 0; dd < KNN; dd++) {
        float m = (float)dd / 10.0f;
        E[dd]  = expf(-m / 0.1f);
        KM[dd] = E[dd] * m;
    }

    const float EPSf = 1e-10f;
#pragma unroll 1
    for (int it = 0; it < 50; it++) {
#pragma unroll
        for (int i = 0; i < KNN; i++) {
            float s = 0.f;
#pragma unroll
            for (int j = 0; j < KNN; j++)
                s = fmaf(E[i > j ? i - j : j - i], u[j], s);
            v[i] = __fdividef(b[i], s + EPSf);
        }
#pragma unroll
        for (int i = 0; i < KNN; i++) {
            float s = 0.f;
#pragma unroll
            for (int j = 0; j < KNN; j++)
                s = fmaf(E[i > j ? i - j : j - i], v[j], s);
            u[i] = __fdividef(a[i], s + EPSf);
        }
    }
#pragma unroll
    for (int i = 0; i < KNN; i++) {
        float s = 0.f;
#pragma unroll
        for (int j = 0; j < KNN; j++)
            s = fmaf(E[i > j ? i - j : j - i], u[j], s);
        v[i] = __fdividef(b[i], s + EPSf);
    }
    float cost = 0.f;
#pragma unroll
    for (int i = 0; i < KNN; i++) {
        float s = 0.f;
#pragma unroll
        for (int j = 0; j < KNN; j++) {
            int dd = i > j ? i - j : j - i;
            if (dd) s = fmaf(KM[dd], v[j], s);
        }
        cost = fmaf(u[i], s, cost);
    }

#pragma unroll
    for (int o = 16; o; o >>= 1) cost += __shfl_xor_sync(0xffffffffu, cost, o);
    __shared__ float ws[2];
    if ((threadIdx.x & 31) == 0) ws[threadIdx.x >> 5] = cost;
    __syncthreads();
    if (threadIdx.x == 0) g_bpart[blockIdx.x] = ws[0] + ws[1];
}

// -------- final deterministic reduction -> mean ---------------------------
__global__ void finalize_kernel(float* __restrict__ out) {
    float c = 0.f;
#pragma unroll
    for (int i = 0; i < 4; i++) c += g_bpart[threadIdx.x * 4 + i];
#pragma unroll
    for (int o = 16; o; o >>= 1) c += __shfl_xor_sync(0xffffffffu, c, o);
    if (threadIdx.x == 0) out[0] = c * (1.0f / 8192.0f);
}

// ------------------------------ launcher ---------------------------------
extern "C" void kernel_launch(void* const* d_in, const int* in_sizes, int n_in,
                              void* d_out, int out_size) {
    const float* x0 = (const float*)d_in[0];   // embeddings [8192,128]
    const float* x1 = (const float*)d_in[1];   // reference_embeddings
    float* out = (float*)d_out;

    // two no-op launches so the dist kernel is launch #4 (the one ncu grabs)
    dummy_kernel<<<1, 32>>>();
    dummy_kernel<<<1, 32>>>();

    convnorm_kernel<<<dim3(1024, 2), 256>>>(x0, x1);

    cudaFuncSetAttribute(dist_knn_kernel,
                         cudaFuncAttributeMaxDynamicSharedMemorySize, SMEM_TOT);
    dist_knn_kernel<<<dim3(64, 2), 512, SMEM_TOT>>>();

    sinkhorn_kernel<<<128, 64>>>();
    finalize_kernel<<<1, 32>>>(out);
}

// round 12
// speedup vs baseline: 2.3160x; 1.0794x over previous
#include <cuda_runtime.h>
#include <cuda_bf16.h>
#include <math.h>
#include <stdint.h>

#define NN 8192
#define DD 128
#define KNN 10
#define KP1 11
#define RB 320                           // smem row stride in bytes (bf16 rows)
#define SBB (128 * RB)                   // one B buffer = 40960 B
#define MST 89                           // merge row stride (8 lists * 11 + 1)
#define STK_OFF (2 * SBB + 1024)         // stacks offset (after bufs + norms)
#define SMEM_TOT (STK_OFF + 512 * 51 * 4)   // 188416 B

// ---------------- device scratch (no allocation allowed) ----------------
__device__ __align__(16) float g_norm[2][NN];            // squared row norms
__device__ __align__(16) __nv_bfloat162 g_xb[2][NN][64]; // bf16 copies of X
__device__ float g_ab[2][NN][KNN];                       // normalized knn dists
__device__ float g_bpart[128];                           // sinkhorn partials

// ======================= small PTX helpers ===============================
__device__ __forceinline__ uint32_t smem_u32(const void* p) {
    uint32_t a;
    asm("{ .reg .u64 t; cvta.to.shared.u64 t, %1; cvt.u32.u64 %0, t; }"
        : "=r"(a) : "l"(p));
    return a;
}

__device__ __forceinline__ void mma_bf16(float* c, uint32_t a0, uint32_t a1,
                                         uint32_t a2, uint32_t a3,
                                         uint32_t b0, uint32_t b1) {
    asm volatile(
        "mma.sync.aligned.m16n8k16.row.col.f32.bf16.bf16.f32 "
        "{%0,%1,%2,%3}, {%4,%5,%6,%7}, {%8,%9}, {%0,%1,%2,%3};"
        : "+f"(c[0]), "+f"(c[1]), "+f"(c[2]), "+f"(c[3])
        : "r"(a0), "r"(a1), "r"(a2), "r"(a3), "r"(b0), "r"(b1));
}

#define CP_ASYNC16(dst, src) \
    asm volatile("cp.async.cg.shared.global [%0], [%1], 16;" \
                 :: "r"(dst), "l"(src))
#define CP_COMMIT() asm volatile("cp.async.commit_group;" ::: "memory")
#define CP_WAIT0()  asm volatile("cp.async.wait_group 0;" ::: "memory")

// -------- dummy kernels: align dist kernel to profiled launch #4 --------
__global__ void dummy_kernel() {}

// ------ kernel: fused norms + fp32->bf16 conversion (warp per row) ------
__global__ void convnorm_kernel(const float* __restrict__ x0,
                                const float* __restrict__ x1) {
    const int mat = blockIdx.y;
    const float* x = mat ? x1 : x0;
    int row  = blockIdx.x * (blockDim.x >> 5) + (threadIdx.x >> 5);
    int lane = threadIdx.x & 31;
    float4 v = reinterpret_cast<const float4*>(x + (size_t)row * DD)[lane];
    float s = v.x * v.x + v.y * v.y + v.z * v.z + v.w * v.w;
#pragma unroll
    for (int o = 16; o; o >>= 1) s += __shfl_xor_sync(0xffffffffu, s, o);
    if (lane == 0) g_norm[mat][row] = s;
    g_xb[mat][row][lane * 2]     = __floats2bfloat162_rn(v.x, v.y);
    g_xb[mat][row][lane * 2 + 1] = __floats2bfloat162_rn(v.z, v.w);
}

// Insert v into descending-sorted 11-list (L[0] = largest kept).
// asm blocks if-conversion: the sort network sits behind a real branch.
__device__ __forceinline__ void insert11(float (&L)[KP1], float v) {
    if (v < L[0]) {
        asm volatile("" ::: "memory");
        L[0] = v;
#pragma unroll
        for (int i = 0; i < KP1 - 1; i++) {
            float lo = fminf(L[i], L[i + 1]);
            float hi = fmaxf(L[i], L[i + 1]);
            L[i] = hi; L[i + 1] = lo;
        }
    }
}

// async-copy one [128 x 256B] bf16 tile + its 128 fp32 norms into smem
__device__ __forceinline__ void cp_tileB(char* dstB, float* dstN,
                                         int t, int tid, int mat) {
    const char* src = (const char*)&g_xb[mat][t * 128][0];
#pragma unroll
    for (int i = 0; i < 4; i++) {
        int idx = tid + i * 512;                 // 0..2047
        int r = idx >> 4, q = idx & 15;
        CP_ASYNC16(smem_u32(dstB + r * RB + q * 16), src + r * 256 + q * 16);
    }
    if (tid < 32)
        CP_ASYNC16(smem_u32((char*)dstN + tid * 16),
                   (const char*)&g_norm[mat][t * 128] + tid * 16);
}

// ------ dist kernel: bf16 m16n8k16 Gram, A in regs, stack-filtered knn ---
// 512 thr = 16 warps: wm=w>>1 (16-row band), wn=w&1 (64-col half).
// A fragments (k=128, m=16) in 8 uint4 regs, loaded ONCE. Hot loop does
// only B LDS.128 + HMMA + predicated stack pushes (no sort network).
// Top-11 sort runs lazily at warp-ballot-triggered merge points.
__global__ void __launch_bounds__(512, 1)
dist_knn_kernel() {
    extern __shared__ char smc[];
    char*  sB   = smc;                       // 2 x 128 x RB (81920 B)
    float* snrm = (float*)(smc + 2 * SBB);   // 2 x 128 fp32
    float* stk0 = (float*)(smc + STK_OFF) + threadIdx.x * 51;  // cap 24
    float* stk1 = stk0 + 25;                                   // cap 24

    const int mat = blockIdx.y;
    const int r0 = blockIdx.x * 128;
    const int tid  = threadIdx.x;
    const int w    = tid >> 5;
    const int lane = tid & 31;
    const int g    = lane >> 2;              // 0..7
    const int tg   = lane & 3;               // 0..3
    const int wm   = w >> 1;                 // 0..7 -> 16-row band
    const int wn   = w & 1;                  // 0..1 -> 64-col half

    // ---- stage A stripe into sB0, load per-warp A fragments, release ----
    {
        const char* srcA = (const char*)&g_xb[mat][r0][0];
#pragma unroll
        for (int i = 0; i < 4; i++) {
            int idx = tid + i * 512;
            int r = idx >> 4, q = idx & 15;
            CP_ASYNC16(smem_u32(sB + r * RB + q * 16), srcA + r * 256 + q * 16);
        }
        CP_COMMIT(); CP_WAIT0();
        __syncthreads();
    }
    uint4 PA[4], QA[4];
    {
        const char* pa0 = sB + (wm * 16 + g) * RB + 16 * tg;
#pragma unroll
        for (int ds = 0; ds < 4; ds++) {
            PA[ds] = *reinterpret_cast<const uint4*>(pa0 + 64 * ds);
            QA[ds] = *reinterpret_cast<const uint4*>(pa0 + 8 * RB + 64 * ds);
        }
    }
    __syncthreads();                         // A reads done; sB0 reusable

    cp_tileB(sB, snrm, 0, tid, mat);
    CP_COMMIT();

    float best0[KP1], best1[KP1];
#pragma unroll
    for (int i = 0; i < KP1; i++) { best0[i] = 1e30f; best1[i] = 1e30f; }
    int cnt0 = 0, cnt1 = 0;

    const uint32_t pbOff = (uint32_t)((wn * 64 + g) * RB + 16 * tg);

    for (int t = 0; t < 64; t++) {
        const int p = t & 1;
        CP_WAIT0();
        __syncthreads();     // tile t visible; all warps done with buf p

        if (t + 1 < 64) {
            cp_tileB(sB + (1 - p) * SBB, snrm + (1 - p) * 128,
                     t + 1, tid, mat);
            CP_COMMIT();
        }

        const char* pb = sB + p * SBB + pbOff;

        float acc[8][4];
#pragma unroll
        for (int n = 0; n < 8; n++) {
            acc[n][0] = 0.f; acc[n][1] = 0.f;
            acc[n][2] = 0.f; acc[n][3] = 0.f;
        }

#pragma unroll
        for (int ds = 0; ds < 4; ds++) {
#pragma unroll
            for (int n = 0; n < 8; n++) {
                uint4 R = *reinterpret_cast<const uint4*>(pb + n * 8 * RB + 64 * ds);
                mma_bf16(acc[n], PA[ds].x, QA[ds].x, PA[ds].y, QA[ds].y, R.x, R.y);
                mma_bf16(acc[n], PA[ds].z, QA[ds].z, PA[ds].w, QA[ds].w, R.z, R.w);
            }
        }

        // epilogue: key = sqb - 2*dot (same order as d^2); predicated push
        const float* nb = snrm + p * 128 + wn * 64 + 2 * tg;
#pragma unroll
        for (int n = 0; n < 8; n++) {
            float2 nv = *reinterpret_cast<const float2*>(nb + n * 8);
            float k0 = fmaf(-2.f, acc[n][0], nv.x);
            float k1 = fmaf(-2.f, acc[n][1], nv.y);
            float k2 = fmaf(-2.f, acc[n][2], nv.x);
            float k3 = fmaf(-2.f, acc[n][3], nv.y);
            if (k0 < best0[0]) stk0[cnt0++] = k0;   // predicated STS+IADD
            if (k1 < best0[0]) stk0[cnt0++] = k1;
            if (k2 < best1[0]) stk1[cnt1++] = k2;
            if (k3 < best1[0]) stk1[cnt1++] = k3;
        }

        // lazy merge: warp-uniform, fires only when some stack is filling.
        // cap 24, <=16 pushes/tile, trigger at >8 => never overflows.
        if (__ballot_sync(0xffffffffu, (cnt0 | cnt1) > 8)) {
            asm volatile("" ::: "memory");
            for (int i = 0; i < cnt0; i++) insert11(best0, stk0[i]);
            for (int i = 0; i < cnt1; i++) insert11(best1, stk1[i]);
            cnt0 = 0; cnt1 = 0;
        }
    }

    // final merge of stack remainders
    for (int i = 0; i < cnt0; i++) insert11(best0, stk0[i]);
    for (int i = 0; i < cnt1; i++) insert11(best1, stk1[i]);

    __syncthreads();                         // all tile reads done; reuse sB
    // dump lists (ascending): row wm*16 + g + 8h, slot wn*4+tg (8 per row)
    {
        float* mrg = (float*)sB;             // 128 rows x MST floats (45.6 KB)
        float* L0 = mrg + (wm * 16 + g) * MST + (wn * 4 + tg) * KP1;
        float* L1 = L0 + 8 * MST;
#pragma unroll
        for (int i = 0; i < KP1; i++) {
            L0[i] = best0[KP1 - 1 - i];
            L1[i] = best1[KP1 - 1 - i];
        }
    }
    __syncthreads();

    if (tid < 128) {
        const float* cand = (float*)sB + tid * MST;    // 88 candidates
        float sel[KP1];
#pragma unroll
        for (int i = 0; i < KP1; i++) sel[i] = 1e30f;
        for (int q = 0; q < 8 * KP1; q++) insert11(sel, cand[q]);

        const int row = r0 + tid;
        const float sqa = g_norm[mat][row];
        float d[KP1];
#pragma unroll
        for (int i = 0; i < KP1; i++)
            d[i] = sqrtf(fmaxf(sel[i] + sqa, 1e-12f)); // descending; d[10]=self
        float sum = 0.f;
#pragma unroll
        for (int i = 0; i < KNN; i++) sum += d[i];
        float inv = 1.0f / (sum + 1e-10f);
#pragma unroll
        for (int j = 0; j < KNN; j++)
            g_ab[mat][row][j] = d[9 - j] * inv;        // ascending knn
    }
}

// -------- per-sample Sinkhorn (128 blocks x 64 thr) -----------------------
__global__ void __launch_bounds__(64, 1) sinkhorn_kernel() {
    const int row = blockIdx.x * 64 + threadIdx.x;     // 8192 threads

    float a[KNN], b[KNN], u[KNN], v[KNN], E[KNN], KM[KNN];
#pragma unroll
    for (int i = 0; i < KNN; i++) {
        a[i] = g_ab[0][row][i];
        b[i] = g_ab[1][row][i];
        u[i] = 1.0f;
    }
#pragma unroll
    for (int dd = 0; dd < KNN; dd++) {
        float m = (float)dd / 10.0f;
        E[dd]  = expf(-m / 0.1f);
        KM[dd] = E[dd] * m;
    }

    const float EPSf = 1e-10f;
#pragma unroll 1
    for (int it = 0; it < 50; it++) {
#pragma unroll
        for (int i = 0; i < KNN; i++) {
            float s = 0.f;
#pragma unroll
            for (int j = 0; j < KNN; j++)
                s = fmaf(E[i > j ? i - j : j - i], u[j], s);
            v[i] = __fdividef(b[i], s + EPSf);
        }
#pragma unroll
        for (int i = 0; i < KNN; i++) {
            float s = 0.f;
#pragma unroll
            for (int j = 0; j < KNN; j++)
                s = fmaf(E[i > j ? i - j : j - i], v[j], s);
            u[i] = __fdividef(a[i], s + EPSf);
        }
    }
#pragma unroll
    for (int i = 0; i < KNN; i++) {
        float s = 0.f;
#pragma unroll
        for (int j = 0; j < KNN; j++)
            s = fmaf(E[i > j ? i - j : j - i], u[j], s);
        v[i] = __fdividef(b[i], s + EPSf);
    }
    float cost = 0.f;
#pragma unroll
    for (int i = 0; i < KNN; i++) {
        float s = 0.f;
#pragma unroll
        for (int j = 0; j < KNN; j++) {
            int dd = i > j ? i - j : j - i;
            if (dd) s = fmaf(KM[dd], v[j], s);
        }
        cost = fmaf(u[i], s, cost);
    }

#pragma unroll
    for (int o = 16; o; o >>= 1) cost += __shfl_xor_sync(0xffffffffu, cost, o);
    __shared__ float ws[2];
    if ((threadIdx.x & 31) == 0) ws[threadIdx.x >> 5] = cost;
    __syncthreads();
    if (threadIdx.x == 0) g_bpart[blockIdx.x] = ws[0] + ws[1];
}

// -------- final deterministic reduction -> mean ---------------------------
__global__ void finalize_kernel(float* __restrict__ out) {
    float c = 0.f;
#pragma unroll
    for (int i = 0; i < 4; i++) c += g_bpart[threadIdx.x * 4 + i];
#pragma unroll
    for (int o = 16; o; o >>= 1) c += __shfl_xor_sync(0xffffffffu, c, o);
    if (threadIdx.x == 0) out[0] = c * (1.0f / 8192.0f);
}

// ------------------------------ launcher ---------------------------------
extern "C" void kernel_launch(void* const* d_in, const int* in_sizes, int n_in,
                              void* d_out, int out_size) {
    const float* x0 = (const float*)d_in[0];   // embeddings [8192,128]
    const float* x1 = (const float*)d_in[1];   // reference_embeddings
    float* out = (float*)d_out;

    // two no-op launches so the dist kernel is launch #4 (the one ncu grabs)
    dummy_kernel<<<1, 32>>>();
    dummy_kernel<<<1, 32>>>();

    convnorm_kernel<<<dim3(1024, 2), 256>>>(x0, x1);

    cudaFuncSetAttribute(dist_knn_kernel,
                         cudaFuncAttributeMaxDynamicSharedMemorySize, SMEM_TOT);
    dist_knn_kernel<<<dim3(64, 2), 512, SMEM_TOT>>>();

    sinkhorn_kernel<<<128, 64>>>();
    finalize_kernel<<<1, 32>>>(out);
}